// round 5
// baseline (speedup 1.0000x reference)
#include <cuda_runtime.h>
#include <cuda_bf16.h>
#include <stdint.h>

#define TH 256
#define TM 64
#define HID 512
#define NIN 16
#define NOUT 136
#define HS 520              // H row stride (bf16): conflict-free for ldmatrix
#define XSTR 24             // X hi/lo row stride (bf16): 48B, 16B-aligned, conflict-free
#define NETS 137

#define XS_OFF  0
#define XH_OFF  4096
#define XL_OFF  (XH_OFF + 3072)
#define HH_OFF  (XL_OFF + 3072)            // 10240
#define HL_OFF  (HH_OFF + 66560)           // 76800
#define NET_OFF (HL_OFF + 66560)           // 143360
#define SMEM_BYTES (NET_OFF + 35072)       // 178432

// fragment-ordered weights: [ks][ng][lane] -> {bhi0, bhi1, blo0, blo1}
__device__ __align__(16) uint4 g_W0f[64 * 32];        // 32 KB  (1 k-step)
__device__ __align__(16) uint4 g_W1f[32 * 64 * 32];   // 1 MB
__device__ __align__(16) uint4 g_W2f[32 * 20 * 32];   // 320 KB (N padded to 160)

__device__ __forceinline__ uint32_t pack_bf2(float a, float b)
{
    __nv_bfloat162 p = __floats2bfloat162_rn(a, b);
    return *(uint32_t*)&p;
}

__device__ __forceinline__ uint4 make_frag(float v00, float v01, float v10, float v11)
{
    float h00 = __bfloat162float(__float2bfloat16(v00));
    float h01 = __bfloat162float(__float2bfloat16(v01));
    float h10 = __bfloat162float(__float2bfloat16(v10));
    float h11 = __bfloat162float(__float2bfloat16(v11));
    uint4 o;
    o.x = pack_bf2(h00, h01);
    o.y = pack_bf2(h10, h11);
    o.z = pack_bf2(v00 - h00, v01 - h01);
    o.w = pack_bf2(v10 - h10, v11 - h11);
    return o;
}

__global__ void prep_weights(const float* __restrict__ W0,
                             const float* __restrict__ W1,
                             const float* __restrict__ W2)
{
    int idx = blockIdx.x * blockDim.x + threadIdx.x;
    const int T0 = 64 * 32;
    const int T1 = 32 * 64 * 32;
    const int T2 = 32 * 20 * 32;
    if (idx < T0) {
        int lane = idx & 31, ng = idx >> 5;
        int g = lane >> 2, t = lane & 3;
        int n = ng * 8 + g;
        int k0 = 2 * t;
        g_W0f[idx] = make_frag(W0[(k0    )*HID + n], W0[(k0 + 1)*HID + n],
                               W0[(k0 + 8)*HID + n], W0[(k0 + 9)*HID + n]);
    } else if (idx < T0 + T1) {
        int i = idx - T0;
        int lane = i & 31, ng = (i >> 5) & 63, ks = i >> 11;
        int g = lane >> 2, t = lane & 3;
        int n = ng * 8 + g;
        int k0 = ks * 16 + 2 * t;
        g_W1f[i] = make_frag(W1[(k0    )*HID + n], W1[(k0 + 1)*HID + n],
                             W1[(k0 + 8)*HID + n], W1[(k0 + 9)*HID + n]);
    } else if (idx < T0 + T1 + T2) {
        int j = idx - T0 - T1;
        int lane = j & 31, ng = (j >> 5) % 20, ks = j / (20 * 32);
        int g = lane >> 2, t = lane & 3;
        int n = ng * 8 + g;
        int k0 = ks * 16 + 2 * t;
        float v00 = (n < NOUT) ? W2[(k0    )*NOUT + n] : 0.0f;
        float v01 = (n < NOUT) ? W2[(k0 + 1)*NOUT + n] : 0.0f;
        float v10 = (n < NOUT) ? W2[(k0 + 8)*NOUT + n] : 0.0f;
        float v11 = (n < NOUT) ? W2[(k0 + 9)*NOUT + n] : 0.0f;
        g_W2f[j] = make_frag(v00, v01, v10, v11);
    }
}

__device__ __forceinline__ void mma16816(float* d, const uint32_t* a,
                                         uint32_t b0, uint32_t b1)
{
    asm volatile(
        "mma.sync.aligned.m16n8k16.row.col.f32.bf16.bf16.f32 "
        "{%0,%1,%2,%3}, {%4,%5,%6,%7}, {%8,%9}, {%0,%1,%2,%3};\n"
        : "+f"(d[0]), "+f"(d[1]), "+f"(d[2]), "+f"(d[3])
        : "r"(a[0]), "r"(a[1]), "r"(a[2]), "r"(a[3]),
          "r"(b0), "r"(b1));
}

__device__ __forceinline__ void ldsm4(uint32_t* r, uint32_t saddr)
{
    asm volatile("ldmatrix.sync.aligned.m8n8.x4.shared.b16 {%0,%1,%2,%3}, [%4];\n"
                 : "=r"(r[0]), "=r"(r[1]), "=r"(r[2]), "=r"(r[3])
                 : "r"(saddr));
}

__device__ __forceinline__ float ftanh(float x)
{
    float xc = fminf(fmaxf(x, -15.0f), 15.0f);
    float e  = __expf(2.0f * xc);
    return __fdividef(e - 1.0f, e + 1.0f);
}

__device__ __forceinline__ void split_store2(__nv_bfloat16* Hh, __nv_bfloat16* Hl,
                                             int idx, float v0, float v1)
{
    __nv_bfloat162 hp = __floats2bfloat162_rn(v0, v1);
    float r0 = v0 - __bfloat162float(hp.x);
    float r1 = v1 - __bfloat162float(hp.y);
    __nv_bfloat162 lp = __floats2bfloat162_rn(r0, r1);
    *(__nv_bfloat162*)(Hh + idx) = hp;
    *(__nv_bfloat162*)(Hl + idx) = lp;
}

__global__ __launch_bounds__(TH, 1)
void ptpd_mma_kernel(const float* __restrict__ pts,
                     const float* __restrict__ b0,
                     const float* __restrict__ b1, const float* __restrict__ b2,
                     float* __restrict__ out)
{
    extern __shared__ char sm[];
    float*          Xs  = (float*)(sm + XS_OFF);
    __nv_bfloat16*  Xh  = (__nv_bfloat16*)(sm + XH_OFF);
    __nv_bfloat16*  Xl  = (__nv_bfloat16*)(sm + XL_OFF);
    __nv_bfloat16*  Hh  = (__nv_bfloat16*)(sm + HH_OFF);
    __nv_bfloat16*  Hl  = (__nv_bfloat16*)(sm + HL_OFF);
    float*          netS = (float*)(sm + NET_OFF);

    const uint32_t smb = (uint32_t)__cvta_generic_to_shared(sm);
    const uint32_t xhS = smb + XH_OFF;
    const uint32_t xlS = smb + XL_OFF;
    const uint32_t hhS = smb + HH_OFF;
    const uint32_t hlS = smb + HL_OFF;

    const int tid  = threadIdx.x;
    const int lane = tid & 31;
    const int wid  = tid >> 5;
    const int g    = lane >> 2;
    const int t    = lane & 3;
    const long row0 = (long)blockIdx.x * TM;

    const int arow  = lane & 15;
    const int acol8 = (lane >> 4) << 3;

    // ---------------- X tile: load fp32 + hi/lo split ----------------
    for (int i = tid; i < TM*NIN; i += TH) {
        float x = pts[row0*NIN + i];
        Xs[i] = x;
        int r = i >> 4, c = i & 15;
        __nv_bfloat16 xh = __float2bfloat16(x);
        Xh[r*XSTR + c] = xh;
        Xl[r*XSTR + c] = __float2bfloat16(x - __bfloat162float(xh));
    }
    __syncthreads();

    // ---------------- layer 0 via MMA (K=16, 2 n-passes) ----------------
    #pragma unroll
    for (int pass = 0; pass < 2; pass++) {
        float acc0[4][4][4];
        #pragma unroll
        for (int nt = 0; nt < 4; nt++) {
            int col = wid*64 + pass*32 + nt*8 + 2*t;
            float bv0 = b0[col], bv1 = b0[col + 1];
            #pragma unroll
            for (int mt = 0; mt < 4; mt++) {
                acc0[mt][nt][0] = bv0; acc0[mt][nt][1] = bv1;
                acc0[mt][nt][2] = bv0; acc0[mt][nt][3] = bv1;
            }
        }
        uint4 bw[4];
        #pragma unroll
        for (int nt = 0; nt < 4; nt++)
            bw[nt] = g_W0f[(wid*8 + pass*4 + nt)*32 + lane];
        uint32_t xhf[4][4], xlf[4][4];
        #pragma unroll
        for (int mt = 0; mt < 4; mt++) {
            int ro = (mt*16 + arow)*XSTR + acol8;
            ldsm4(xhf[mt], xhS + ro*2);
            ldsm4(xlf[mt], xlS + ro*2);
        }
        #pragma unroll
        for (int nt = 0; nt < 4; nt++)
            #pragma unroll
            for (int mt = 0; mt < 4; mt++) {
                mma16816(acc0[mt][nt], xhf[mt], bw[nt].x, bw[nt].y);
                mma16816(acc0[mt][nt], xhf[mt], bw[nt].z, bw[nt].w);
                mma16816(acc0[mt][nt], xlf[mt], bw[nt].x, bw[nt].y);
            }
        // tanh + split -> H0
        #pragma unroll
        for (int mt = 0; mt < 4; mt++)
            #pragma unroll
            for (int nt = 0; nt < 4; nt++) {
                int r   = mt*16 + g;
                int col = wid*64 + pass*32 + nt*8 + 2*t;
                split_store2(Hh, Hl, r*HS + col,
                             ftanh(acc0[mt][nt][0]), ftanh(acc0[mt][nt][1]));
                split_store2(Hh, Hl, (r + 8)*HS + col,
                             ftanh(acc0[mt][nt][2]), ftanh(acc0[mt][nt][3]));
            }
    }
    __syncthreads();

    // =============== layer 1: warp owns 64 n-cols, all 64 rows; B double-buffered ===============
    {
        float acc1[4][8][4];
        #pragma unroll
        for (int nt = 0; nt < 8; nt++) {
            int col = wid*64 + nt*8 + 2*t;
            float bv0 = b1[col], bv1 = b1[col + 1];
            #pragma unroll
            for (int mt = 0; mt < 4; mt++) {
                acc1[mt][nt][0] = bv0; acc1[mt][nt][1] = bv1;
                acc1[mt][nt][2] = bv0; acc1[mt][nt][3] = bv1;
            }
        }

        uint4 bcur[8];
        #pragma unroll
        for (int nt = 0; nt < 8; nt++)
            bcur[nt] = g_W1f[(wid*8 + nt)*32 + lane];

        for (int ks = 0; ks < 32; ks++) {
            uint32_t ah[4][4], al[4][4];
            #pragma unroll
            for (int mt = 0; mt < 4; mt++) {
                int ro = (mt*16 + arow)*HS + ks*16 + acol8;
                ldsm4(ah[mt], hhS + ro*2);
                ldsm4(al[mt], hlS + ro*2);
            }
            uint4 bnxt[8];
            if (ks < 31) {
                #pragma unroll
                for (int nt = 0; nt < 8; nt++)
                    bnxt[nt] = g_W1f[((ks + 1)*64 + wid*8 + nt)*32 + lane];
            }
            #pragma unroll
            for (int nt = 0; nt < 8; nt++)
                #pragma unroll
                for (int mt = 0; mt < 4; mt++) {
                    mma16816(acc1[mt][nt], ah[mt], bcur[nt].x, bcur[nt].y);
                    mma16816(acc1[mt][nt], ah[mt], bcur[nt].z, bcur[nt].w);
                    mma16816(acc1[mt][nt], al[mt], bcur[nt].x, bcur[nt].y);
                }
            #pragma unroll
            for (int nt = 0; nt < 8; nt++) bcur[nt] = bnxt[nt];
        }

        __syncthreads();    // all warps done READING H0 before overwrite

        // tanh + split -> H1 (overwrites H0 buffers)
        #pragma unroll
        for (int mt = 0; mt < 4; mt++)
            #pragma unroll
            for (int nt = 0; nt < 8; nt++) {
                int r   = mt*16 + g;
                int col = wid*64 + nt*8 + 2*t;
                split_store2(Hh, Hl, r*HS + col,
                             ftanh(acc1[mt][nt][0]), ftanh(acc1[mt][nt][1]));
                split_store2(Hh, Hl, (r + 8)*HS + col,
                             ftanh(acc1[mt][nt][2]), ftanh(acc1[mt][nt][3]));
            }
    }
    __syncthreads();

    // =============== layer 2: 2 m-warps x 4 n-warps (N padded 160); B double-buffered ===============
    {
        const int wm = wid & 1;
        const int wn = wid >> 1;
        float acc2[2][5][4];
        #pragma unroll
        for (int nt = 0; nt < 5; nt++) {
            int col = wn*40 + nt*8 + 2*t;
            float bv0 = (col     < NOUT) ? b2[col]     : 0.0f;
            float bv1 = (col + 1 < NOUT) ? b2[col + 1] : 0.0f;
            #pragma unroll
            for (int mt = 0; mt < 2; mt++) {
                acc2[mt][nt][0] = bv0; acc2[mt][nt][1] = bv1;
                acc2[mt][nt][2] = bv0; acc2[mt][nt][3] = bv1;
            }
        }

        uint4 bcur[5];
        #pragma unroll
        for (int nt = 0; nt < 5; nt++)
            bcur[nt] = g_W2f[(wn*5 + nt)*32 + lane];

        for (int ks = 0; ks < 32; ks++) {
            uint32_t ah[2][4], al[2][4];
            #pragma unroll
            for (int mt = 0; mt < 2; mt++) {
                int ro = (wm*32 + mt*16 + arow)*HS + ks*16 + acol8;
                ldsm4(ah[mt], hhS + ro*2);
                ldsm4(al[mt], hlS + ro*2);
            }
            uint4 bnxt[5];
            if (ks < 31) {
                #pragma unroll
                for (int nt = 0; nt < 5; nt++)
                    bnxt[nt] = g_W2f[((ks + 1)*20 + wn*5 + nt)*32 + lane];
            }
            #pragma unroll
            for (int nt = 0; nt < 5; nt++)
                #pragma unroll
                for (int mt = 0; mt < 2; mt++) {
                    mma16816(acc2[mt][nt], ah[mt], bcur[nt].x, bcur[nt].y);
                    mma16816(acc2[mt][nt], ah[mt], bcur[nt].z, bcur[nt].w);
                    mma16816(acc2[mt][nt], al[mt], bcur[nt].x, bcur[nt].y);
                }
            #pragma unroll
            for (int nt = 0; nt < 5; nt++) bcur[nt] = bnxt[nt];
        }

        // net -> smem
        #pragma unroll
        for (int mt = 0; mt < 2; mt++)
            #pragma unroll
            for (int nt = 0; nt < 5; nt++) {
                int r   = wm*32 + mt*16 + g;
                int col = wn*40 + nt*8 + 2*t;
                if (col + 1 < NOUT) {
                    netS[r*NETS + col]           = acc2[mt][nt][0];
                    netS[r*NETS + col + 1]       = acc2[mt][nt][1];
                    netS[(r + 8)*NETS + col]     = acc2[mt][nt][2];
                    netS[(r + 8)*NETS + col + 1] = acc2[mt][nt][3];
                }
            }
    }
    __syncthreads();

    // ---------------- quadratic form ----------------
    if (tid < TM) {
        const float* nn = netS + tid*NETS;
        const float* xv = Xs + tid*NIN;
        float x[NIN], sx = 0.0f;
        #pragma unroll
        for (int i = 0; i < NIN; i++) { x[i] = xv[i]; sx = fmaf(x[i], x[i], sx); }
        float y[NIN];
        #pragma unroll
        for (int j = 0; j < NIN; j++) y[j] = 0.0f;
        int tt = 0;
        #pragma unroll
        for (int i = 0; i < NIN; i++) {
            #pragma unroll
            for (int j = 0; j <= i; j++) {
                y[j] = fmaf(nn[tt], x[i], y[j]);
                tt++;
            }
        }
        float v = 0.0f;
        #pragma unroll
        for (int j = 0; j < NIN; j++) v = fmaf(y[j], y[j], v);
        out[row0 + tid] = v + 1e-6f * sx;
    }
}

extern "C" void kernel_launch(void* const* d_in, const int* in_sizes, int n_in,
                              void* d_out, int out_size)
{
    const float* pts = (const float*)d_in[0];
    const float* W0  = (const float*)d_in[1];
    const float* b0  = (const float*)d_in[2];
    const float* W1  = (const float*)d_in[3];
    const float* b1  = (const float*)d_in[4];
    const float* W2  = (const float*)d_in[5];
    const float* b2  = (const float*)d_in[6];
    float* out = (float*)d_out;

    const int B = in_sizes[0] / NIN;

    cudaFuncSetAttribute(ptpd_mma_kernel,
                         cudaFuncAttributeMaxDynamicSharedMemorySize, SMEM_BYTES);

    const int prep_threads = 64*32 + 32*64*32 + 32*20*32;
    prep_weights<<<(prep_threads + 255)/256, 256>>>(W0, W1, W2);

    ptpd_mma_kernel<<<B/TM, TH, SMEM_BYTES>>>(pts, b0, b1, b2, out);
}